// round 2
// baseline (speedup 1.0000x reference)
#include <cuda_runtime.h>
#include <cuda_bf16.h>
#include <math.h>

// ---------------- problem constants ----------------
#define NNODES   100000
#define NEDGES   200000
#define EMBD     300
#define LD       320            // padded feature stride (K and N pad)
#define MPAD     100096         // 782 * 128
#define NGR      4096
#define FEAT     256
#define HFEAT    128
#define NLAYER   5

// ---------------- device scratch ----------------
__device__ float g_bufH[(size_t)MPAD * LD];   // h   (layer input / BN output)
__device__ float g_bufX[(size_t)MPAD * LD];   // hx  (GEMM output)
__device__ float g_Wpad[LD * LD];
__device__ float g_colsum[LD];
__device__ float g_colsq[LD];
__device__ int   g_deg[NNODES + 1];
__device__ int   g_rowptr[NNODES + 1];
__device__ int   g_cursor[NNODES];
__device__ int   g_entries[NEDGES];
__device__ float g_sums[NGR * EMBD];
__device__ int   g_counts[NGR];
__device__ float g_hg[NGR * EMBD];

// ---------------- embed: h = emb1[at] + emb2[ch], zero padding ----------------
__global__ void embed_kernel(const int* __restrict__ at, const int* __restrict__ ch,
                             const float* __restrict__ e1, const float* __restrict__ e2,
                             int N) {
    int r = blockIdx.x;              // 0..MPAD-1
    int f = threadIdx.x;             // 0..319
    float v = 0.f;
    if (r < N && f < EMBD) {
        v = e1[(size_t)at[r] * EMBD + f] + e2[(size_t)ch[r] * EMBD + f];
    }
    g_bufH[(size_t)r * LD + f] = v;
}

// ---------------- CSR build ----------------
__global__ void zero_deg_kernel(int N) {
    int i = blockIdx.x * blockDim.x + threadIdx.x;
    if (i <= N) g_deg[i] = 0;
}
__global__ void count_kernel(const int* __restrict__ colp, int E) {
    int e = blockIdx.x * blockDim.x + threadIdx.x;
    if (e < E) atomicAdd(&g_deg[colp[e]], 1);
}
// single-block exclusive scan of g_deg[0..N) -> g_rowptr, rowptr[N]=total
__global__ void scan_kernel(int N) {
    __shared__ int warpsum[32];
    __shared__ int carry;
    int tid = threadIdx.x, lane = tid & 31, wid = tid >> 5;
    if (tid == 0) carry = 0;
    __syncthreads();
    for (int base = 0; base < N; base += 1024) {
        int i = base + tid;
        int v = (i < N) ? g_deg[i] : 0;
        int x = v;
        #pragma unroll
        for (int off = 1; off < 32; off <<= 1) {
            int y = __shfl_up_sync(0xFFFFFFFFu, x, off);
            if (lane >= off) x += y;
        }
        if (lane == 31) warpsum[wid] = x;
        __syncthreads();
        if (wid == 0) {
            int w = warpsum[lane];
            #pragma unroll
            for (int off = 1; off < 32; off <<= 1) {
                int y = __shfl_up_sync(0xFFFFFFFFu, w, off);
                if (lane >= off) w += y;
            }
            warpsum[lane] = w;
        }
        __syncthreads();
        int woff = (wid > 0) ? warpsum[wid - 1] : 0;
        int incl = x + woff + carry;
        if (i < N) g_rowptr[i] = incl - v;   // exclusive
        __syncthreads();
        if (tid == 1023) carry = incl;
        __syncthreads();
    }
    if (tid == 0) g_rowptr[N] = carry;
}
__global__ void copy_cursor_kernel(int N) {
    int i = blockIdx.x * blockDim.x + threadIdx.x;
    if (i < N) g_cursor[i] = g_rowptr[i];
}
__global__ void fill_kernel(const int* __restrict__ rowp, const int* __restrict__ colp,
                            const int* __restrict__ et, const int* __restrict__ ed, int E) {
    int e = blockIdx.x * blockDim.x + threadIdx.x;
    if (e >= E) return;
    int c = colp[e];
    int pos = atomicAdd(&g_cursor[c], 1);
    g_entries[pos] = rowp[e] | (et[e] << 20) | (ed[e] << 23);
}

// ---------------- W padding (300x300 -> 320x320 zero-padded) ----------------
__global__ void wpad_kernel(const float* __restrict__ Wl) {
    int k = blockIdx.x, n = threadIdx.x;    // 320 x 320
    g_Wpad[k * LD + n] = (k < EMBD && n < EMBD) ? Wl[k * EMBD + n] : 0.f;
}

// ---------------- SGEMM: bufX = bufH(MPADx320) @ Wpad(320x320) ----------------
// BM=128, BN=64, BK=16, 256 threads, 8x4 per thread
__global__ __launch_bounds__(256) void sgemm_kernel() {
    __shared__ __align__(16) float As[16][128];
    __shared__ __align__(16) float Bs[16][64];
    int tid = threadIdx.x;
    int bm = blockIdx.y * 128;
    int bn = blockIdx.x * 64;
    int tr = tid >> 4, tc = tid & 15;
    float acc[8][4];
    #pragma unroll
    for (int i = 0; i < 8; i++)
        #pragma unroll
        for (int j = 0; j < 4; j++) acc[i][j] = 0.f;

    const float* A = g_bufH;
    int am = tid >> 2;             // 0..63
    int akk = (tid & 3) * 4;       // 0,4,8,12
    int bkk = tid >> 4;            // 0..15
    int bn4 = (tid & 15) * 4;      // 0..60

    for (int k0 = 0; k0 < LD; k0 += 16) {
        float4 v0 = *(const float4*)&A[(size_t)(bm + am) * LD + k0 + akk];
        float4 v1 = *(const float4*)&A[(size_t)(bm + am + 64) * LD + k0 + akk];
        As[akk + 0][am] = v0.x; As[akk + 1][am] = v0.y;
        As[akk + 2][am] = v0.z; As[akk + 3][am] = v0.w;
        As[akk + 0][am + 64] = v1.x; As[akk + 1][am + 64] = v1.y;
        As[akk + 2][am + 64] = v1.z; As[akk + 3][am + 64] = v1.w;
        *(float4*)&Bs[bkk][bn4] = *(const float4*)&g_Wpad[(k0 + bkk) * LD + bn + bn4];
        __syncthreads();
        #pragma unroll
        for (int kk = 0; kk < 16; kk++) {
            float a[8], b[4];
            *(float4*)&a[0] = *(const float4*)&As[kk][tr * 8];
            *(float4*)&a[4] = *(const float4*)&As[kk][tr * 8 + 4];
            *(float4*)&b[0] = *(const float4*)&Bs[kk][tc * 4];
            #pragma unroll
            for (int i = 0; i < 8; i++)
                #pragma unroll
                for (int j = 0; j < 4; j++)
                    acc[i][j] = fmaf(a[i], b[j], acc[i][j]);
        }
        __syncthreads();
    }
    #pragma unroll
    for (int i = 0; i < 8; i++) {
        size_t r = (size_t)(bm + tr * 8 + i) * LD + bn + tc * 4;
        float4 o; o.x = acc[i][0]; o.y = acc[i][1]; o.z = acc[i][2]; o.w = acc[i][3];
        *(float4*)&g_bufX[r] = o;
    }
}

// ---------------- aggregation: bufH[v] = b + hx[v] + sl + sum_in (hx[src]+esc) ----------------
__global__ __launch_bounds__(128) void aggregate_kernel(
        const float* __restrict__ ee1_l, const float* __restrict__ ee2_l,
        const float* __restrict__ b_l) {
    int v = blockIdx.x;
    int t = threadIdx.x;   // 128 threads; features t, t+128, t+256
    float sl = ee1_l[4] + ee2_l[0];
    const float* hv = g_bufX + (size_t)v * LD;
    bool has2 = (t + 256 < EMBD);
    float a0 = hv[t]       + b_l[t]       + sl;
    float a1 = hv[t + 128] + b_l[t + 128] + sl;
    float a2 = has2 ? (hv[t + 256] + b_l[t + 256] + sl) : 0.f;
    int s = g_rowptr[v], e = g_rowptr[v + 1];
    for (int i = s; i < e; i++) {
        int p = g_entries[i];
        int src = p & 0xFFFFF;
        float esc = ee1_l[(p >> 20) & 7] + ee2_l[(p >> 23) & 3];
        const float* hs = g_bufX + (size_t)src * LD;
        a0 += hs[t] + esc;
        a1 += hs[t + 128] + esc;
        if (has2) a2 += hs[t + 256] + esc;
    }
    float* ov = g_bufH + (size_t)v * LD;
    ov[t] = a0; ov[t + 128] = a1;
    if (has2) ov[t + 256] = a2;
}

// ---------------- BN stats ----------------
__global__ void zero_stats_kernel() {
    int i = blockIdx.x * blockDim.x + threadIdx.x;
    if (i < LD) { g_colsum[i] = 0.f; g_colsq[i] = 0.f; }
}
__global__ __launch_bounds__(320) void colreduce_kernel(int N) {
    int f = threadIdx.x;
    if (f >= EMBD) return;
    int r0 = blockIdx.x * 256;
    int rend = min(r0 + 256, N);
    float s = 0.f, q = 0.f;
    for (int r = r0; r < rend; r++) {
        float x = g_bufH[(size_t)r * LD + f];
        s += x; q += x * x;
    }
    atomicAdd(&g_colsum[f], s);
    atomicAdd(&g_colsq[f], q);
}
__global__ __launch_bounds__(320) void bnnorm_kernel(
        const float* __restrict__ gamma_l, const float* __restrict__ beta_l,
        int N, int do_relu) {
    int f = threadIdx.x;
    if (f >= EMBD) return;
    const float invN = 1.0f / (float)N;
    float mean = g_colsum[f] * invN;
    float var  = g_colsq[f] * invN - mean * mean;
    float scale = gamma_l[f] * rsqrtf(var + 1e-5f);
    float shift = beta_l[f] - mean * scale;
    int r0 = blockIdx.x * 16;
    int rend = min(r0 + 16, N);
    for (int r = r0; r < rend; r++) {
        size_t idx = (size_t)r * LD + f;
        float y = g_bufH[idx] * scale + shift;
        if (do_relu) y = fmaxf(y, 0.f);
        g_bufH[idx] = y;
    }
}

// ---------------- pooling ----------------
__global__ void zero_pool_kernel() {
    int i = blockIdx.x * blockDim.x + threadIdx.x;
    if (i < NGR * EMBD) g_sums[i] = 0.f;
    if (i < NGR) g_counts[i] = 0;
}
__global__ __launch_bounds__(320) void pool_kernel(const int* __restrict__ batch, int N) {
    int v = blockIdx.x;
    int t = threadIdx.x;
    int g = batch[v];
    if (t < EMBD) atomicAdd(&g_sums[(size_t)g * EMBD + t], g_bufH[(size_t)v * LD + t]);
    if (t == 300) atomicAdd(&g_counts[g], 1);
}
__global__ __launch_bounds__(320) void hg_kernel() {
    int g = blockIdx.x;
    int t = threadIdx.x;
    if (t >= EMBD) return;
    float cnt = fmaxf((float)g_counts[g], 1.0f);
    g_hg[(size_t)g * EMBD + t] = g_sums[(size_t)g * EMBD + t] / cnt;
}

// ---------------- hf = hg @ feat_W + feat_b (writes directly to d_out) ----------------
__global__ __launch_bounds__(256) void featgemm_kernel(
        const float* __restrict__ fw, const float* __restrict__ fb,
        float* __restrict__ hf) {
    __shared__ __align__(16) float s[8 * EMBD];
    int g0 = blockIdx.x * 8;
    int j = threadIdx.x;  // 0..255
    for (int idx = j; idx < 8 * EMBD; idx += 256)
        s[idx] = g_hg[(size_t)g0 * EMBD + idx];
    __syncthreads();
    float acc[8];
    float bb = fb[j];
    #pragma unroll
    for (int i = 0; i < 8; i++) acc[i] = bb;
    for (int k = 0; k < EMBD; k++) {
        float w = fw[k * FEAT + j];
        #pragma unroll
        for (int i = 0; i < 8; i++) acc[i] = fmaf(s[i * EMBD + k], w, acc[i]);
    }
    #pragma unroll
    for (int i = 0; i < 8; i++)
        hf[(size_t)(g0 + i) * FEAT + j] = acc[i];
}

// ---------------- head: pred = softplus(hf@W1+b1)@W2 + b2 ----------------
__device__ __forceinline__ float softplus_f(float x) {
    return fmaxf(x, 0.f) + log1pf(expf(-fabsf(x)));
}
__global__ __launch_bounds__(128) void head_kernel(
        const float* __restrict__ hf,
        const float* __restrict__ W1, const float* __restrict__ b1,
        const float* __restrict__ W2, const float* __restrict__ b2,
        float* __restrict__ pred) {
    __shared__ __align__(16) float s[8 * FEAT];
    __shared__ float redA[8][4], redB[8][4];
    int g0 = blockIdx.x * 8;
    int j = threadIdx.x;  // 0..127
    for (int idx = j; idx < 8 * FEAT; idx += 128)
        s[idx] = hf[(size_t)g0 * FEAT + idx];
    __syncthreads();
    float acc[8];
    float bb = b1[j];
    #pragma unroll
    for (int i = 0; i < 8; i++) acc[i] = bb;
    for (int k = 0; k < FEAT; k++) {
        float w = W1[k * HFEAT + j];
        #pragma unroll
        for (int i = 0; i < 8; i++) acc[i] = fmaf(s[i * FEAT + k], w, acc[i]);
    }
    float w0 = W2[j * 2], w1 = W2[j * 2 + 1];
    int lane = j & 31, wid = j >> 5;
    #pragma unroll
    for (int i = 0; i < 8; i++) {
        float tv = softplus_f(acc[i]);
        float v0 = tv * w0, v1 = tv * w1;
        #pragma unroll
        for (int off = 16; off > 0; off >>= 1) {
            v0 += __shfl_down_sync(0xFFFFFFFFu, v0, off);
            v1 += __shfl_down_sync(0xFFFFFFFFu, v1, off);
        }
        if (lane == 0) { redA[i][wid] = v0; redB[i][wid] = v1; }
    }
    __syncthreads();
    if (j < 8) {
        float p0 = redA[j][0] + redA[j][1] + redA[j][2] + redA[j][3] + b2[0];
        float p1 = redB[j][0] + redB[j][1] + redB[j][2] + redB[j][3] + b2[1];
        pred[(size_t)(g0 + j) * 2 + 0] = p0;
        pred[(size_t)(g0 + j) * 2 + 1] = p1;
    }
}

// ---------------- launch ----------------
extern "C" void kernel_launch(void* const* d_in, const int* in_sizes, int n_in,
                              void* d_out, int out_size) {
    const int*   atom_type = (const int*)d_in[0];
    const int*   chirality = (const int*)d_in[1];
    const int*   edge_index = (const int*)d_in[2];
    const int*   edge_type = (const int*)d_in[3];
    const int*   edge_dir  = (const int*)d_in[4];
    const int*   batch     = (const int*)d_in[5];
    const float* atom_emb1 = (const float*)d_in[6];
    const float* atom_emb2 = (const float*)d_in[7];
    const float* W         = (const float*)d_in[8];
    const float* b         = (const float*)d_in[9];
    const float* ee1       = (const float*)d_in[10];
    const float* ee2       = (const float*)d_in[11];
    const float* bn_gamma  = (const float*)d_in[12];
    const float* bn_beta   = (const float*)d_in[13];
    const float* feat_W    = (const float*)d_in[14];
    const float* feat_b    = (const float*)d_in[15];
    const float* head_W1   = (const float*)d_in[16];
    const float* head_b1   = (const float*)d_in[17];
    const float* head_W2   = (const float*)d_in[18];
    const float* head_b2   = (const float*)d_in[19];

    int N = in_sizes[0];
    int E = in_sizes[3];
    const int* rowp = edge_index;
    const int* colp = edge_index + E;

    float* out_hf   = (float*)d_out;
    float* out_pred = (float*)d_out + (size_t)NGR * FEAT;

    // node embeddings + zero all padding
    embed_kernel<<<MPAD, 320>>>(atom_type, chirality, atom_emb1, atom_emb2, N);

    // CSR by destination
    zero_deg_kernel<<<(N + 256) / 256, 256>>>(N);
    count_kernel<<<(E + 255) / 256, 256>>>(colp, E);
    scan_kernel<<<1, 1024>>>(N);
    copy_cursor_kernel<<<(N + 255) / 256, 256>>>(N);
    fill_kernel<<<(E + 255) / 256, 256>>>(rowp, colp, edge_type, edge_dir, E);

    for (int l = 0; l < NLAYER; l++) {
        wpad_kernel<<<LD, LD>>>(W + (size_t)l * EMBD * EMBD);
        sgemm_kernel<<<dim3(LD / 64, MPAD / 128), 256>>>();
        aggregate_kernel<<<N, 128>>>(ee1 + l * 5, ee2 + l * 3, b + (size_t)l * EMBD);
        zero_stats_kernel<<<2, 256>>>();
        colreduce_kernel<<<(N + 255) / 256, 320>>>(N);
        bnnorm_kernel<<<(N + 15) / 16, 320>>>(bn_gamma + (size_t)l * EMBD,
                                              bn_beta + (size_t)l * EMBD,
                                              N, (l < NLAYER - 1) ? 1 : 0);
    }

    // global mean pool
    zero_pool_kernel<<<(NGR * EMBD + 255) / 256, 256>>>();
    pool_kernel<<<N, 320>>>(batch, N);
    hg_kernel<<<NGR, 320>>>();

    // feature + head
    featgemm_kernel<<<NGR / 8, 256>>>(feat_W, feat_b, out_hf);
    head_kernel<<<NGR / 8, 128>>>(out_hf, head_W1, head_b1, head_W2, head_b2, out_pred);
}

// round 8
// speedup vs baseline: 1.4714x; 1.4714x over previous
#include <cuda_runtime.h>
#include <cuda_bf16.h>
#include <math.h>
#include <stdint.h>

// ---------------- problem constants ----------------
#define NNODES   100000
#define NEDGES   200000
#define EMBD     300
#define LD       320            // padded feature stride (K and N pad)
#define MPAD     100096         // 782 * 128
#define NGR      4096
#define FEAT     256
#define HFEAT    128
#define NLAYER   5
#define NTILES   98             // ceil(NNODES/1024)

// ---------------- device scratch ----------------
__device__ float g_bufH[(size_t)MPAD * LD];   // h   (layer input / BN output), fp32
__device__ float g_bufX[(size_t)MPAD * LD];   // hx  (GEMM output), fp32
__device__ __align__(16) __nv_bfloat16 g_hbf_hi[(size_t)MPAD * LD];  // bf16 split of h
__device__ __align__(16) __nv_bfloat16 g_hbf_lo[(size_t)MPAD * LD];
__device__ __align__(16) __nv_bfloat16 g_wt_hi[NLAYER * LD * LD];    // W^T bf16 split [l][n][k]
__device__ __align__(16) __nv_bfloat16 g_wt_lo[NLAYER * LD * LD];
__device__ float g_colsum[LD];
__device__ float g_colsq[LD];
__device__ int   g_deg[NNODES + 1];
__device__ int   g_rowptr[NNODES + 1];
__device__ int   g_cursor[NNODES];
__device__ int   g_entries[NEDGES];
__device__ int   g_tilesum[NTILES];
__device__ int   g_tileoff[NTILES];
__device__ float g_sums[NGR * EMBD];
__device__ int   g_counts[NGR];
__device__ float g_hg[NGR * EMBD];

// ---------------- helpers ----------------
__device__ __forceinline__ uint32_t smem_u32(const void* p) {
    uint32_t a;
    asm("{ .reg .u64 t; cvta.to.shared.u64 t, %1; cvt.u32.u64 %0, t; }" : "=r"(a) : "l"(p));
    return a;
}

static __device__ __forceinline__ void split_bf16(float x, __nv_bfloat16& hi, __nv_bfloat16& lo) {
    hi = __float2bfloat16(x);
    lo = __float2bfloat16(x - __bfloat162float(hi));
}

__device__ __forceinline__ void ldsm_x4(uint32_t addr, uint32_t* r) {
    asm volatile("ldmatrix.sync.aligned.m8n8.x4.shared.b16 {%0,%1,%2,%3}, [%4];"
                 : "=r"(r[0]), "=r"(r[1]), "=r"(r[2]), "=r"(r[3]) : "r"(addr));
}

__device__ __forceinline__ void mma16816(float* c, const uint32_t* a, const uint32_t* b) {
    asm volatile(
        "mma.sync.aligned.m16n8k16.row.col.f32.bf16.bf16.f32 "
        "{%0,%1,%2,%3}, {%4,%5,%6,%7}, {%8,%9}, {%0,%1,%2,%3};"
        : "+f"(c[0]), "+f"(c[1]), "+f"(c[2]), "+f"(c[3])
        : "r"(a[0]), "r"(a[1]), "r"(a[2]), "r"(a[3]), "r"(b[0]), "r"(b[1]));
}

// ---------------- embed: h = emb1[at] + emb2[ch], zero padding, + bf16 split ----------------
__global__ void embed_kernel(const int* __restrict__ at, const int* __restrict__ ch,
                             const float* __restrict__ e1, const float* __restrict__ e2,
                             int N) {
    int r = blockIdx.x;              // 0..MPAD-1
    int f = threadIdx.x;             // 0..319
    float v = 0.f;
    if (r < N && f < EMBD) {
        v = e1[(size_t)at[r] * EMBD + f] + e2[(size_t)ch[r] * EMBD + f];
    }
    size_t idx = (size_t)r * LD + f;
    g_bufH[idx] = v;
    __nv_bfloat16 hi, lo;
    split_bf16(v, hi, lo);
    g_hbf_hi[idx] = hi;
    g_hbf_lo[idx] = lo;
}

// ---------------- W^T bf16 split: wt[l][n][k] = split(W[l][k][n]) ----------------
__global__ void conv_w_kernel(const float* __restrict__ W) {
    int n = blockIdx.x, l = blockIdx.y, k = threadIdx.x;   // 320 x 5, 320 threads
    float v = (n < EMBD && k < EMBD) ? W[((size_t)l * EMBD + k) * EMBD + n] : 0.f;
    __nv_bfloat16 hi, lo;
    split_bf16(v, hi, lo);
    size_t idx = ((size_t)l * LD + n) * LD + k;
    g_wt_hi[idx] = hi;
    g_wt_lo[idx] = lo;
}

// ---------------- CSR build ----------------
__global__ void zero_deg_kernel(int N) {
    int i = blockIdx.x * blockDim.x + threadIdx.x;
    if (i <= N) g_deg[i] = 0;
}
__global__ void count_kernel(const int* __restrict__ colp, int E) {
    int e = blockIdx.x * blockDim.x + threadIdx.x;
    if (e < E) atomicAdd(&g_deg[colp[e]], 1);
}
// tiled scan: phase 1 — per-1024 block local exclusive scan + tile totals
__global__ void scan1_kernel(int N) {
    __shared__ int ws[32];
    int tid = threadIdx.x, lane = tid & 31, w = tid >> 5;
    int i = blockIdx.x * 1024 + tid;
    int v = (i < N) ? g_deg[i] : 0;
    int x = v;
    #pragma unroll
    for (int o = 1; o < 32; o <<= 1) {
        int y = __shfl_up_sync(0xFFFFFFFFu, x, o);
        if (lane >= o) x += y;
    }
    if (lane == 31) ws[w] = x;
    __syncthreads();
    if (w == 0) {
        int t = ws[lane];
        #pragma unroll
        for (int o = 1; o < 32; o <<= 1) {
            int y = __shfl_up_sync(0xFFFFFFFFu, t, o);
            if (lane >= o) t += y;
        }
        ws[lane] = t;
    }
    __syncthreads();
    int incl = x + (w ? ws[w - 1] : 0);
    if (i < N) g_rowptr[i] = incl - v;
    if (tid == 1023) g_tilesum[blockIdx.x] = incl;
}
// phase 2 — single block scans the tile totals
__global__ void scan2_kernel(int T, int N) {
    __shared__ int ws[4];
    int tid = threadIdx.x, lane = tid & 31, w = tid >> 5;   // 128 threads
    int v = (tid < T) ? g_tilesum[tid] : 0;
    int x = v;
    #pragma unroll
    for (int o = 1; o < 32; o <<= 1) {
        int y = __shfl_up_sync(0xFFFFFFFFu, x, o);
        if (lane >= o) x += y;
    }
    if (lane == 31) ws[w] = x;
    __syncthreads();
    int add = 0;
    for (int j = 0; j < w; j++) add += ws[j];
    int incl = x + add;
    if (tid < T) g_tileoff[tid] = incl - v;
    if (tid == T - 1) g_rowptr[N] = incl;
}
// phase 3 — add tile offsets, also init cursor
__global__ void scan3_kernel(int N) {
    int i = blockIdx.x * 1024 + threadIdx.x;
    if (i < N) {
        int v = g_rowptr[i] + g_tileoff[blockIdx.x];
        g_rowptr[i] = v;
        g_cursor[i] = v;
    }
}
__global__ void fill_kernel(const int* __restrict__ rowp, const int* __restrict__ colp,
                            const int* __restrict__ et, const int* __restrict__ ed, int E) {
    int e = blockIdx.x * blockDim.x + threadIdx.x;
    if (e >= E) return;
    int c = colp[e];
    int pos = atomicAdd(&g_cursor[c], 1);
    g_entries[pos] = rowp[e] | (et[e] << 20) | (ed[e] << 23);
}

// ---------------- HMMA 3xBF16 GEMM: bufX = h(MPADx320) @ W(320x320) ----------------
// CTA tile 128x64, BK=32, 8 warps as 4(M)x2(N), warp tile 32x32.
// SMEM rows padded to 40 bf16 (80B) -> conflict-free ldmatrix.
#define ASTR 40

__global__ __launch_bounds__(256) void hmma_gemm_kernel(int layer) {
    __shared__ __align__(16) __nv_bfloat16 sAh[128 * ASTR], sAl[128 * ASTR];
    __shared__ __align__(16) __nv_bfloat16 sBh[64 * ASTR],  sBl[64 * ASTR];
    int tid = threadIdx.x, wid = tid >> 5, lane = tid & 31;
    int bm = blockIdx.y * 128, bn = blockIdx.x * 64;
    int wm = (wid & 3) * 32;       // warp M offset in tile
    int wn = (wid >> 2) * 32;      // warp N offset in tile

    const __nv_bfloat16* Ah = g_hbf_hi + (size_t)bm * LD;
    const __nv_bfloat16* Al = g_hbf_lo + (size_t)bm * LD;
    const __nv_bfloat16* Bh = g_wt_hi + ((size_t)layer * LD + bn) * LD;
    const __nv_bfloat16* Bl = g_wt_lo + ((size_t)layer * LD + bn) * LD;

    float acc[2][4][4];
    #pragma unroll
    for (int i = 0; i < 2; i++)
        #pragma unroll
        for (int j = 0; j < 4; j++)
            #pragma unroll
            for (int q = 0; q < 4; q++) acc[i][j][q] = 0.f;

    uint32_t sAh0 = smem_u32(sAh), sAl0 = smem_u32(sAl);
    uint32_t sBh0 = smem_u32(sBh), sBl0 = smem_u32(sBl);

    // ldmatrix lane addressing (bytes)
    int a_row = wm + (lane & 15);
    int a_kof = (lane >> 4) * 8;
    uint32_t aoff = (uint32_t)(a_row * ASTR + a_kof) * 2;
    int b_nn = wn + (lane & 7) + ((lane >> 4) & 1) * 8;   // + nj*8 added per-frag-pair
    int b_kof = ((lane >> 3) & 1) * 8;
    uint32_t boff = (uint32_t)(b_nn * ASTR + b_kof) * 2;

    for (int k0 = 0; k0 < LD; k0 += 32) {
        __syncthreads();
        // load A tiles: 128 rows x 32 k, 16B chunks; 2 chunks/thread/plane
        #pragma unroll
        for (int it = 0; it < 2; it++) {
            int idx = it * 256 + tid;
            int r = idx >> 2, c = idx & 3;
            *(uint4*)&sAh[r * ASTR + c * 8] = *(const uint4*)&Ah[(size_t)r * LD + k0 + c * 8];
            *(uint4*)&sAl[r * ASTR + c * 8] = *(const uint4*)&Al[(size_t)r * LD + k0 + c * 8];
        }
        // load B tiles: 64 rows x 32 k; 1 chunk/thread/plane
        {
            int r = tid >> 2, c = tid & 3;
            *(uint4*)&sBh[r * ASTR + c * 8] = *(const uint4*)&Bh[(size_t)r * LD + k0 + c * 8];
            *(uint4*)&sBl[r * ASTR + c * 8] = *(const uint4*)&Bl[(size_t)r * LD + k0 + c * 8];
        }
        __syncthreads();

        #pragma unroll
        for (int k16 = 0; k16 < 2; k16++) {
            uint32_t kbyte = (uint32_t)(k16 * 16) * 2;
            uint32_t afh[2][4], afl[2][4];
            #pragma unroll
            for (int mi = 0; mi < 2; mi++) {
                uint32_t o = aoff + (uint32_t)(mi * 16 * ASTR) * 2 + kbyte;
                ldsm_x4(sAh0 + o, afh[mi]);
                ldsm_x4(sAl0 + o, afl[mi]);
            }
            uint32_t bfh[4][2], bfl[4][2];
            #pragma unroll
            for (int nj = 0; nj < 4; nj += 2) {
                uint32_t o = boff + (uint32_t)(nj * 8 * ASTR) * 2 + kbyte;
                uint32_t t[4];
                ldsm_x4(sBh0 + o, t);
                bfh[nj][0] = t[0]; bfh[nj][1] = t[1];
                bfh[nj + 1][0] = t[2]; bfh[nj + 1][1] = t[3];
                ldsm_x4(sBl0 + o, t);
                bfl[nj][0] = t[0]; bfl[nj][1] = t[1];
                bfl[nj + 1][0] = t[2]; bfl[nj + 1][1] = t[3];
            }
            #pragma unroll
            for (int mi = 0; mi < 2; mi++)
                #pragma unroll
                for (int ni = 0; ni < 4; ni++) {
                    mma16816(acc[mi][ni], afh[mi], bfh[ni]);
                    mma16816(acc[mi][ni], afh[mi], bfl[ni]);
                    mma16816(acc[mi][ni], afl[mi], bfh[ni]);
                }
        }
    }

    // epilogue: c-frag layout -> g_bufX
    int qr = lane >> 2, qc = (lane & 3) * 2;
    #pragma unroll
    for (int mi = 0; mi < 2; mi++) {
        int row0 = bm + wm + mi * 16 + qr;
        #pragma unroll
        for (int ni = 0; ni < 4; ni++) {
            int col = bn + wn + ni * 8 + qc;
            float2 v0; v0.x = acc[mi][ni][0]; v0.y = acc[mi][ni][1];
            float2 v1; v1.x = acc[mi][ni][2]; v1.y = acc[mi][ni][3];
            *(float2*)&g_bufX[(size_t)row0 * LD + col] = v0;
            *(float2*)&g_bufX[(size_t)(row0 + 8) * LD + col] = v1;
        }
    }
}

// ---------------- aggregation: bufH[v] = b + hx[v] + sl + sum_in (hx[src]+esc) ----------------
__global__ __launch_bounds__(128) void aggregate_kernel(
        const float* __restrict__ ee1_l, const float* __restrict__ ee2_l,
        const float* __restrict__ b_l) {
    int v = blockIdx.x;
    int t = threadIdx.x;   // 128 threads; features t, t+128, t+256
    float sl = ee1_l[4] + ee2_l[0];
    const float* hv = g_bufX + (size_t)v * LD;
    bool has2 = (t + 256 < EMBD);
    float a0 = hv[t]       + b_l[t]       + sl;
    float a1 = hv[t + 128] + b_l[t + 128] + sl;
    float a2 = has2 ? (hv[t + 256] + b_l[t + 256] + sl) : 0.f;
    int s = g_rowptr[v], e = g_rowptr[v + 1];
    for (int i = s; i < e; i++) {
        int p = g_entries[i];
        int src = p & 0xFFFFF;
        float esc = ee1_l[(p >> 20) & 7] + ee2_l[(p >> 23) & 3];
        const float* hs = g_bufX + (size_t)src * LD;
        a0 += hs[t] + esc;
        a1 += hs[t + 128] + esc;
        if (has2) a2 += hs[t + 256] + esc;
    }
    float* ov = g_bufH + (size_t)v * LD;
    ov[t] = a0; ov[t + 128] = a1;
    if (has2) ov[t + 256] = a2;
}

// ---------------- BN stats ----------------
__global__ void zero_stats_kernel() {
    int i = blockIdx.x * blockDim.x + threadIdx.x;
    if (i < LD) { g_colsum[i] = 0.f; g_colsq[i] = 0.f; }
}
__global__ __launch_bounds__(320) void colreduce_kernel(int N) {
    int f = threadIdx.x;
    if (f >= EMBD) return;
    int r0 = blockIdx.x * 256;
    int rend = min(r0 + 256, N);
    float s = 0.f, q = 0.f;
    for (int r = r0; r < rend; r++) {
        float x = g_bufH[(size_t)r * LD + f];
        s += x; q += x * x;
    }
    atomicAdd(&g_colsum[f], s);
    atomicAdd(&g_colsq[f], q);
}
__global__ __launch_bounds__(320) void bnnorm_kernel(
        const float* __restrict__ gamma_l, const float* __restrict__ beta_l,
        int N, int do_relu) {
    int f = threadIdx.x;
    if (f >= EMBD) return;
    const float invN = 1.0f / (float)N;
    float mean = g_colsum[f] * invN;
    float var  = g_colsq[f] * invN - mean * mean;
    float scale = gamma_l[f] * rsqrtf(var + 1e-5f);
    float shift = beta_l[f] - mean * scale;
    int r0 = blockIdx.x * 16;
    int rend = min(r0 + 16, N);
    for (int r = r0; r < rend; r++) {
        size_t idx = (size_t)r * LD + f;
        float y = g_bufH[idx] * scale + shift;
        if (do_relu) y = fmaxf(y, 0.f);
        g_bufH[idx] = y;
        __nv_bfloat16 hi, lo;
        split_bf16(y, hi, lo);
        g_hbf_hi[idx] = hi;
        g_hbf_lo[idx] = lo;
    }
}

// ---------------- pooling ----------------
__global__ void zero_pool_kernel() {
    int i = blockIdx.x * blockDim.x + threadIdx.x;
    if (i < NGR * EMBD) g_sums[i] = 0.f;
    if (i < NGR) g_counts[i] = 0;
}
__global__ __launch_bounds__(320) void pool_kernel(const int* __restrict__ batch, int N) {
    int v = blockIdx.x;
    int t = threadIdx.x;
    int g = batch[v];
    if (t < EMBD) atomicAdd(&g_sums[(size_t)g * EMBD + t], g_bufH[(size_t)v * LD + t]);
    if (t == 300) atomicAdd(&g_counts[g], 1);
}
__global__ __launch_bounds__(320) void hg_kernel() {
    int g = blockIdx.x;
    int t = threadIdx.x;
    if (t >= EMBD) return;
    float cnt = fmaxf((float)g_counts[g], 1.0f);
    g_hg[(size_t)g * EMBD + t] = g_sums[(size_t)g * EMBD + t] / cnt;
}

// ---------------- hf = hg @ feat_W + feat_b ----------------
__global__ __launch_bounds__(256) void featgemm_kernel(
        const float* __restrict__ fw, const float* __restrict__ fb,
        float* __restrict__ hf) {
    __shared__ __align__(16) float s[8 * EMBD];
    int g0 = blockIdx.x * 8;
    int j = threadIdx.x;  // 0..255
    for (int idx = j; idx < 8 * EMBD; idx += 256)
        s[idx] = g_hg[(size_t)g0 * EMBD + idx];
    __syncthreads();
    float acc[8];
    float bb = fb[j];
    #pragma unroll
    for (int i = 0; i < 8; i++) acc[i] = bb;
    for (int k = 0; k < EMBD; k++) {
        float w = fw[k * FEAT + j];
        #pragma unroll
        for (int i = 0; i < 8; i++) acc[i] = fmaf(s[i * EMBD + k], w, acc[i]);
    }
    #pragma unroll
    for (int i = 0; i < 8; i++)
        hf[(size_t)(g0 + i) * FEAT + j] = acc[i];
}

// ---------------- head: pred = softplus(hf@W1+b1)@W2 + b2 ----------------
__device__ __forceinline__ float softplus_f(float x) {
    return fmaxf(x, 0.f) + log1pf(expf(-fabsf(x)));
}
__global__ __launch_bounds__(128) void head_kernel(
        const float* __restrict__ hf,
        const float* __restrict__ W1, const float* __restrict__ b1,
        const float* __restrict__ W2, const float* __restrict__ b2,
        float* __restrict__ pred) {
    __shared__ __align__(16) float s[8 * FEAT];
    __shared__ float redA[8][4], redB[8][4];
    int g0 = blockIdx.x * 8;
    int j = threadIdx.x;  // 0..127
    for (int idx = j; idx < 8 * FEAT; idx += 128)
        s[idx] = hf[(size_t)g0 * FEAT + idx];
    __syncthreads();
    float acc[8];
    float bb = b1[j];
    #pragma unroll
    for (int i = 0; i < 8; i++) acc[i] = bb;
    for (int k = 0; k < FEAT; k++) {
        float w = W1[k * HFEAT + j];
        #pragma unroll
        for (int i = 0; i < 8; i++) acc[i] = fmaf(s[i * FEAT + k], w, acc[i]);
    }
    float w0 = W2[j * 2], w1 = W2[j * 2 + 1];
    int lane = j & 31, wid = j >> 5;
    #pragma unroll
    for (int i = 0; i < 8; i++) {
        float tv = softplus_f(acc[i]);
        float v0 = tv * w0, v1 = tv * w1;
        #pragma unroll
        for (int off = 16; off > 0; off >>= 1) {
            v0 += __shfl_down_sync(0xFFFFFFFFu, v0, off);
            v1 += __shfl_down_sync(0xFFFFFFFFu, v1, off);
        }
        if (lane == 0) { redA[i][wid] = v0; redB[i][wid] = v1; }
    }
    __syncthreads();
    if (j < 8) {
        float p0 = redA[j][0] + redA[j][1] + redA[j][2] + redA[j][3] + b2[0];
        float p1 = redB[j][0] + redB[j][1] + redB[j][2] + redB[j][3] + b2[1];
        pred[(size_t)(g0 + j) * 2 + 0] = p0;
        pred[(size_t)(g0 + j) * 2 + 1] = p1;
    }
}

// ---------------- launch ----------------
extern "C" void kernel_launch(void* const* d_in, const int* in_sizes, int n_in,
                              void* d_out, int out_size) {
    const int*   atom_type = (const int*)d_in[0];
    const int*   chirality = (const int*)d_in[1];
    const int*   edge_index = (const int*)d_in[2];
    const int*   edge_type = (const int*)d_in[3];
    const int*   edge_dir  = (const int*)d_in[4];
    const int*   batch     = (const int*)d_in[5];
    const float* atom_emb1 = (const float*)d_in[6];
    const float* atom_emb2 = (const float*)d_in[7];
    const float* W         = (const float*)d_in[8];
    const float* b         = (const float*)d_in[9];
    const float* ee1       = (const float*)d_in[10];
    const float* ee2       = (const float*)d_in[11];
    const float* bn_gamma  = (const float*)d_in[12];
    const float* bn_beta   = (const float*)d_in[13];
    const float* feat_W    = (const float*)d_in[14];
    const float* feat_b    = (const float*)d_in[15];
    const float* head_W1   = (const float*)d_in[16];
    const float* head_b1   = (const float*)d_in[17];
    const float* head_W2   = (const float*)d_in[18];
    const float* head_b2   = (const float*)d_in[19];

    int N = in_sizes[0];
    int E = in_sizes[3];
    const int* rowp = edge_index;
    const int* colp = edge_index + E;

    float* out_hf   = (float*)d_out;
    float* out_pred = (float*)d_out + (size_t)NGR * FEAT;

    // node embeddings + zero all padding (fp32 + bf16 hi/lo)
    embed_kernel<<<MPAD, 320>>>(atom_type, chirality, atom_emb1, atom_emb2, N);
    // W^T bf16 split for all layers
    conv_w_kernel<<<dim3(LD, NLAYER), LD>>>(W);

    // CSR by destination
    zero_deg_kernel<<<(N + 256) / 256, 256>>>(N);
    count_kernel<<<(E + 255) / 256, 256>>>(colp, E);
    scan1_kernel<<<NTILES, 1024>>>(N);
    scan2_kernel<<<1, 128>>>(NTILES, N);
    scan3_kernel<<<NTILES, 1024>>>(N);
    fill_kernel<<<(E + 255) / 256, 256>>>(rowp, colp, edge_type, edge_dir, E);

    for (int l = 0; l < NLAYER; l++) {
        hmma_gemm_kernel<<<dim3(LD / 64, MPAD / 128), 256>>>(l);
        aggregate_kernel<<<N, 128>>>(ee1 + l * 5, ee2 + l * 3, b + (size_t)l * EMBD);
        zero_stats_kernel<<<2, 256>>>();
        colreduce_kernel<<<(N + 255) / 256, 320>>>(N);
        bnnorm_kernel<<<(N + 15) / 16, 320>>>(bn_gamma + (size_t)l * EMBD,
                                              bn_beta + (size_t)l * EMBD,
                                              N, (l < NLAYER - 1) ? 1 : 0);
    }

    // global mean pool
    zero_pool_kernel<<<(NGR * EMBD + 255) / 256, 256>>>();
    pool_kernel<<<N, 320>>>(batch, N);
    hg_kernel<<<NGR, 320>>>();

    // feature + head
    featgemm_kernel<<<NGR / 8, 256>>>(feat_W, feat_b, out_hf);
    head_kernel<<<NGR / 8, 128>>>(out_hf, head_W1, head_b1, head_W2, head_b2, out_pred);
}